// round 5
// baseline (speedup 1.0000x reference)
#include <cuda_runtime.h>

#define BB 64
#define TT 512
#define DD 768
#define VV 20
#define NEGC (-1000000000.0f)
#define NCH 16            // t-chunks for k1
#define TCH (TT / NCH)    // 32 tokens per k1 chunk
#define NC3 32            // t-chunks for fused pooling kernel
#define TC3 (TT / NC3)    // 16 tokens per k3 chunk
#define D4 (DD / 4)       // 192 float4 per row

// Scratch (no device allocation allowed)
__device__ __align__(16) float g_p1[NCH * BB * DD];  // k1 partials
__device__ __align__(16) float g_u[NC3 * BB * DD];   // k3 unnormalized pooled partials
__device__ float g_m[NC3 * BB];                      // k3 chunk-local max
__device__ float g_z[NC3 * BB];                      // k3 chunk-local exp-sum
__device__ float g_scores[BB * TT];                  // raw pooling scores

// ---------------------------------------------------------------------------
// K1: partial masked sums. grid (NCH, B), block 192 (thread per float4 col)
// ---------------------------------------------------------------------------
__global__ __launch_bounds__(192) void k1_msum(const float4* __restrict__ emb,
                                               const int* __restrict__ emask) {
    int b = blockIdx.y;
    int c = blockIdx.x;
    int t0 = c * TCH;
    int tid = threadIdx.x;
    __shared__ float sm[TCH];
    if (tid < TCH)
        sm[tid] = (float)emask[b * TT + t0 + tid];
    __syncthreads();

    const float4* e = emb + (size_t)(b * TT + t0) * D4 + tid;
    float4 acc = make_float4(0.f, 0.f, 0.f, 0.f);
    float4 r[8];
#pragma unroll
    for (int i = 0; i < 8; i++) r[i] = e[(size_t)i * D4];

#pragma unroll
    for (int base = 0; base < TCH; base += 8) {
        float4 n[8];
        if (base + 8 < TCH) {
#pragma unroll
            for (int i = 0; i < 8; i++)
                n[i] = e[(size_t)(base + 8 + i) * D4];
        }
#pragma unroll
        for (int i = 0; i < 8; i++) {
            float m = sm[base + i];
            acc.x = fmaf(m, r[i].x, acc.x);
            acc.y = fmaf(m, r[i].y, acc.y);
            acc.z = fmaf(m, r[i].z, acc.z);
            acc.w = fmaf(m, r[i].w, acc.w);
        }
        if (base + 8 < TCH) {
#pragma unroll
            for (int i = 0; i < 8; i++) r[i] = n[i];
        }
    }
    ((float4*)g_p1)[(size_t)(c * BB + b) * D4 + tid] = acc;
}

// ---------------------------------------------------------------------------
// K2: reduce msum partials, value softmax over V=20, value_embedding.
// grid B, block 768
// ---------------------------------------------------------------------------
__global__ void k2_value(const float* __restrict__ W,
                         const int* __restrict__ vmask,
                         float* __restrict__ out_ve,
                         float* __restrict__ out_vp) {
    int b = blockIdx.x;
    int tid = threadIdx.x;
    int warp = tid >> 5;
    int lane = tid & 31;
    __shared__ float s_ms[DD];
    __shared__ float s_sc[VV];
    __shared__ float s_p[VV];

    {
        float acc = 0.f;
#pragma unroll
        for (int c = 0; c < NCH; c++)
            acc += g_p1[(size_t)(c * BB + b) * DD + tid];
        s_ms[tid] = acc;
    }
    __syncthreads();

    if (warp < VV) {
        const float* w = W + warp * DD;
        float acc = 0.f;
#pragma unroll
        for (int d = lane; d < DD; d += 32)
            acc += s_ms[d] * w[d];
#pragma unroll
        for (int o = 16; o; o >>= 1)
            acc += __shfl_xor_sync(0xffffffffu, acc, o);
        if (lane == 0)
            s_sc[warp] = acc + (1.0f - (float)vmask[b * VV + warp]) * NEGC;
    }
    __syncthreads();

    if (tid < 32) {
        float v = (tid < VV) ? s_sc[tid] : -3.4e38f;
        float mx = v;
#pragma unroll
        for (int o = 16; o; o >>= 1)
            mx = fmaxf(mx, __shfl_xor_sync(0xffffffffu, mx, o));
        float ev = (tid < VV) ? expf(v - mx) : 0.f;
        float s = ev;
#pragma unroll
        for (int o = 16; o; o >>= 1)
            s += __shfl_xor_sync(0xffffffffu, s, o);
        float p = ev / s;
        if (tid < VV) {
            s_p[tid] = p;
            out_vp[b * VV + tid] = p;
        }
    }
    __syncthreads();

    float acc = 0.f;
#pragma unroll
    for (int v = 0; v < VV; v++)
        acc += s_p[v] * W[v * DD + tid];
    out_ve[b * DD + tid] = acc;
}

// ---------------------------------------------------------------------------
// K3 (fused scores + online-softmax pooling, single emb pass).
// grid (NC3, B), block 192. Each thread holds its 16-token x float4 column
// slice in registers; scores via warp shuffle reduce; chunk-local softmax
// stats; unnormalized weighted sum straight from registers.
// ---------------------------------------------------------------------------
__global__ __launch_bounds__(192) void k3_fused(const float4* __restrict__ emb,
                                                const int* __restrict__ emask,
                                                const float4* __restrict__ ve) {
    int b = blockIdx.y;
    int c = blockIdx.x;
    int t0 = c * TC3;
    int tid = threadIdx.x;
    int warp = tid >> 5;
    int lane = tid & 31;

    __shared__ float red[TC3][6];
    __shared__ float s_e[TC3];

    float4 ve4 = ve[b * D4 + tid];

    const float4* e = emb + (size_t)(b * TT + t0) * D4 + tid;
    float4 r[TC3];
#pragma unroll
    for (int t = 0; t < TC3; t++)
        r[t] = e[(size_t)t * D4];

    // per-token partial dots -> warp reduce -> smem
#pragma unroll
    for (int t = 0; t < TC3; t++) {
        float p = r[t].x * ve4.x + r[t].y * ve4.y +
                  r[t].z * ve4.z + r[t].w * ve4.w;
#pragma unroll
        for (int o = 16; o; o >>= 1)
            p += __shfl_xor_sync(0xffffffffu, p, o);
        if (lane == 0) red[t][warp] = p;
    }
    __syncthreads();

    // threads 0..15 (all in warp 0): finalize scores, chunk-local m/Z
    if (tid < TC3) {
        float s = red[tid][0] + red[tid][1] + red[tid][2] +
                  red[tid][3] + red[tid][4] + red[tid][5];
        s += (1.0f - (float)emask[b * TT + t0 + tid]) * NEGC;
        g_scores[b * TT + t0 + tid] = s;

        float m = s;
#pragma unroll
        for (int o = 8; o; o >>= 1)
            m = fmaxf(m, __shfl_xor_sync(0x0000ffffu, m, o));
        float ez = expf(s - m);
        s_e[tid] = ez;
        float z = ez;
#pragma unroll
        for (int o = 8; o; o >>= 1)
            z += __shfl_xor_sync(0x0000ffffu, z, o);
        if (tid == 0) {
            g_m[c * BB + b] = m;
            g_z[c * BB + b] = z;
        }
    }
    __syncthreads();

    // unnormalized weighted sum directly from registers
    float4 acc = make_float4(0.f, 0.f, 0.f, 0.f);
#pragma unroll
    for (int t = 0; t < TC3; t++) {
        float w = s_e[t];
        acc.x = fmaf(w, r[t].x, acc.x);
        acc.y = fmaf(w, r[t].y, acc.y);
        acc.z = fmaf(w, r[t].z, acc.z);
        acc.w = fmaf(w, r[t].w, acc.w);
    }
    ((float4*)g_u)[(size_t)(c * BB + b) * D4 + tid] = acc;
}

// ---------------------------------------------------------------------------
// K4: combine chunk stats -> pooled embedding + pooling probs.
// grid B, block 192.
// ---------------------------------------------------------------------------
__global__ __launch_bounds__(192) void k4_combine(float* __restrict__ out_pooled,
                                                  float* __restrict__ out_pp) {
    int b = blockIdx.x;
    int tid = threadIdx.x;
    __shared__ float s_w[NC3];
    __shared__ float s_m, s_z;

    if (tid < 32) {
        float m = g_m[tid * BB + b];
        float mm = m;
#pragma unroll
        for (int o = 16; o; o >>= 1)
            mm = fmaxf(mm, __shfl_xor_sync(0xffffffffu, mm, o));
        float w = expf(m - mm);
        s_w[tid] = w;
        float z = g_z[tid * BB + b] * w;
#pragma unroll
        for (int o = 16; o; o >>= 1)
            z += __shfl_xor_sync(0xffffffffu, z, o);
        if (tid == 0) { s_m = mm; s_z = z; }
    }
    __syncthreads();

    float inv = 1.0f / s_z;
    float gm = s_m;

    float4 acc = make_float4(0.f, 0.f, 0.f, 0.f);
#pragma unroll
    for (int c = 0; c < NC3; c++) {
        float w = s_w[c];
        float4 u = ((const float4*)g_u)[(size_t)(c * BB + b) * D4 + tid];
        acc.x = fmaf(w, u.x, acc.x);
        acc.y = fmaf(w, u.y, acc.y);
        acc.z = fmaf(w, u.z, acc.z);
        acc.w = fmaf(w, u.w, acc.w);
    }
    acc.x *= inv; acc.y *= inv; acc.z *= inv; acc.w *= inv;
    ((float4*)out_pooled)[b * D4 + tid] = acc;

#pragma unroll
    for (int t = tid; t < TT; t += 192)
        out_pp[b * TT + t] = expf(g_scores[b * TT + t] - gm) * inv;
}

// ---------------------------------------------------------------------------
extern "C" void kernel_launch(void* const* d_in, const int* in_sizes, int n_in,
                              void* d_out, int out_size) {
    const float* emb = (const float*)d_in[0];      // (B,T,D) f32
    const int* emask = (const int*)d_in[1];        // (B,T) i32
    const int* vmask = (const int*)d_in[2];        // (B,V) i32
    const float* W = (const float*)d_in[3];        // (V,D) f32

    float* out = (float*)d_out;
    float* out_ve = out;                            // (B,D)
    float* out_pooled = out + BB * DD;              // (B,D)
    float* out_vp = out + 2 * BB * DD;              // (B,V)
    float* out_pp = out + 2 * BB * DD + BB * VV;    // (B,T)

    k1_msum<<<dim3(NCH, BB), 192>>>((const float4*)emb, emask);
    k2_value<<<BB, 768>>>(W, vmask, out_ve, out_vp);
    k3_fused<<<dim3(NC3, BB), 192>>>((const float4*)emb, emask,
                                     (const float4*)out_ve);
    k4_combine<<<BB, 192>>>(out_pooled, out_pp);
}

// round 6
// speedup vs baseline: 1.0757x; 1.0757x over previous
#include <cuda_runtime.h>

#define BB 64
#define TT 512
#define DD 768
#define VV 20
#define NEGC (-1000000000.0f)
#define NCH 16            // t-chunks for k1
#define TCH (TT / NCH)    // 32 tokens per k1 chunk
#define NC3 32            // t-chunks for fused pooling kernel
#define TC3 (TT / NC3)    // 16 tokens per k3 chunk
#define D4 (DD / 4)       // 192 float4 per row
#define NS4 4             // k4 D-splits
#define DS4 (D4 / NS4)    // 48 float4 columns per k4 block

// Scratch (no device allocation allowed)
__device__ __align__(16) float g_p1[NCH * BB * DD];  // k1 partials
__device__ __align__(16) float g_u[NC3 * BB * DD];   // k3 unnormalized pooled partials
__device__ float g_m[NC3 * BB];                      // k3 chunk-local max
__device__ float g_z[NC3 * BB];                      // k3 chunk-local exp-sum
__device__ float g_scores[BB * TT];                  // raw pooling scores

// ---------------------------------------------------------------------------
// K1: partial masked sums. grid (NCH, B), block 192 (thread per float4 col)
// ---------------------------------------------------------------------------
__global__ __launch_bounds__(192) void k1_msum(const float4* __restrict__ emb,
                                               const int* __restrict__ emask) {
    int b = blockIdx.y;
    int c = blockIdx.x;
    int t0 = c * TCH;
    int tid = threadIdx.x;
    __shared__ float sm[TCH];
    if (tid < TCH)
        sm[tid] = (float)emask[b * TT + t0 + tid];
    __syncthreads();

    const float4* e = emb + (size_t)(b * TT + t0) * D4 + tid;
    float4 acc = make_float4(0.f, 0.f, 0.f, 0.f);
    float4 r[8];
#pragma unroll
    for (int i = 0; i < 8; i++) r[i] = e[(size_t)i * D4];

#pragma unroll
    for (int base = 0; base < TCH; base += 8) {
        float4 n[8];
        if (base + 8 < TCH) {
#pragma unroll
            for (int i = 0; i < 8; i++)
                n[i] = e[(size_t)(base + 8 + i) * D4];
        }
#pragma unroll
        for (int i = 0; i < 8; i++) {
            float m = sm[base + i];
            acc.x = fmaf(m, r[i].x, acc.x);
            acc.y = fmaf(m, r[i].y, acc.y);
            acc.z = fmaf(m, r[i].z, acc.z);
            acc.w = fmaf(m, r[i].w, acc.w);
        }
        if (base + 8 < TCH) {
#pragma unroll
            for (int i = 0; i < 8; i++) r[i] = n[i];
        }
    }
    ((float4*)g_p1)[(size_t)(c * BB + b) * D4 + tid] = acc;
}

// ---------------------------------------------------------------------------
// K2: reduce msum partials, value softmax over V=20, value_embedding.
// grid B, block 768
// ---------------------------------------------------------------------------
__global__ void k2_value(const float* __restrict__ W,
                         const int* __restrict__ vmask,
                         float* __restrict__ out_ve,
                         float* __restrict__ out_vp) {
    int b = blockIdx.x;
    int tid = threadIdx.x;
    int warp = tid >> 5;
    int lane = tid & 31;
    __shared__ float s_ms[DD];
    __shared__ float s_sc[VV];
    __shared__ float s_p[VV];

    {
        float acc = 0.f;
#pragma unroll
        for (int c = 0; c < NCH; c++)
            acc += g_p1[(size_t)(c * BB + b) * DD + tid];
        s_ms[tid] = acc;
    }
    __syncthreads();

    if (warp < VV) {
        const float* w = W + warp * DD;
        float acc = 0.f;
#pragma unroll
        for (int d = lane; d < DD; d += 32)
            acc += s_ms[d] * w[d];
#pragma unroll
        for (int o = 16; o; o >>= 1)
            acc += __shfl_xor_sync(0xffffffffu, acc, o);
        if (lane == 0)
            s_sc[warp] = acc + (1.0f - (float)vmask[b * VV + warp]) * NEGC;
    }
    __syncthreads();

    if (tid < 32) {
        float v = (tid < VV) ? s_sc[tid] : -3.4e38f;
        float mx = v;
#pragma unroll
        for (int o = 16; o; o >>= 1)
            mx = fmaxf(mx, __shfl_xor_sync(0xffffffffu, mx, o));
        float ev = (tid < VV) ? expf(v - mx) : 0.f;
        float s = ev;
#pragma unroll
        for (int o = 16; o; o >>= 1)
            s += __shfl_xor_sync(0xffffffffu, s, o);
        float p = ev / s;
        if (tid < VV) {
            s_p[tid] = p;
            out_vp[b * VV + tid] = p;
        }
    }
    __syncthreads();

    float acc = 0.f;
#pragma unroll
    for (int v = 0; v < VV; v++)
        acc += s_p[v] * W[v * DD + tid];
    out_ve[b * DD + tid] = acc;
}

// ---------------------------------------------------------------------------
// K3 (fused scores + online-softmax pooling, single emb pass).
// grid (NC3, B), block 192.
// ---------------------------------------------------------------------------
__global__ __launch_bounds__(192) void k3_fused(const float4* __restrict__ emb,
                                                const int* __restrict__ emask,
                                                const float4* __restrict__ ve) {
    int b = blockIdx.y;
    int c = blockIdx.x;
    int t0 = c * TC3;
    int tid = threadIdx.x;
    int warp = tid >> 5;
    int lane = tid & 31;

    __shared__ float red[TC3][6];
    __shared__ float s_e[TC3];

    float4 ve4 = ve[b * D4 + tid];

    const float4* e = emb + (size_t)(b * TT + t0) * D4 + tid;
    float4 r[TC3];
#pragma unroll
    for (int t = 0; t < TC3; t++)
        r[t] = e[(size_t)t * D4];

#pragma unroll
    for (int t = 0; t < TC3; t++) {
        float p = r[t].x * ve4.x + r[t].y * ve4.y +
                  r[t].z * ve4.z + r[t].w * ve4.w;
#pragma unroll
        for (int o = 16; o; o >>= 1)
            p += __shfl_xor_sync(0xffffffffu, p, o);
        if (lane == 0) red[t][warp] = p;
    }
    __syncthreads();

    if (tid < TC3) {
        float s = red[tid][0] + red[tid][1] + red[tid][2] +
                  red[tid][3] + red[tid][4] + red[tid][5];
        s += (1.0f - (float)emask[b * TT + t0 + tid]) * NEGC;
        g_scores[b * TT + t0 + tid] = s;

        float m = s;
#pragma unroll
        for (int o = 8; o; o >>= 1)
            m = fmaxf(m, __shfl_xor_sync(0x0000ffffu, m, o));
        float ez = expf(s - m);
        s_e[tid] = ez;
        float z = ez;
#pragma unroll
        for (int o = 8; o; o >>= 1)
            z += __shfl_xor_sync(0x0000ffffu, z, o);
        if (tid == 0) {
            g_m[c * BB + b] = m;
            g_z[c * BB + b] = z;
        }
    }
    __syncthreads();

    float4 acc = make_float4(0.f, 0.f, 0.f, 0.f);
#pragma unroll
    for (int t = 0; t < TC3; t++) {
        float w = s_e[t];
        acc.x = fmaf(w, r[t].x, acc.x);
        acc.y = fmaf(w, r[t].y, acc.y);
        acc.z = fmaf(w, r[t].z, acc.z);
        acc.w = fmaf(w, r[t].w, acc.w);
    }
    ((float4*)g_u)[(size_t)(c * BB + b) * D4 + tid] = acc;
}

// ---------------------------------------------------------------------------
// K4: combine chunk stats -> pooled embedding + pooling probs.
// grid (NS4, B) = 256 blocks, block 192.
// Each block: recompute stats (tiny), reduce a 48-float4 D-slice with 4-way
// chunk split across threads, write its pp token slice.
// ---------------------------------------------------------------------------
__global__ __launch_bounds__(192) void k4_combine(float* __restrict__ out_pooled,
                                                  float* __restrict__ out_pp) {
    int b = blockIdx.y;
    int x = blockIdx.x;
    int tid = threadIdx.x;
    __shared__ float s_w[NC3];
    __shared__ float s_m, s_z;
    __shared__ float4 s_acc[NS4][DS4];

    // stats (warp 0, redundant per block — 64 B from L2)
    if (tid < 32) {
        float m = g_m[tid * BB + b];
        float mm = m;
#pragma unroll
        for (int o = 16; o; o >>= 1)
            mm = fmaxf(mm, __shfl_xor_sync(0xffffffffu, mm, o));
        float w = expf(m - mm);
        s_w[tid] = w;
        float z = g_z[tid * BB + b] * w;
#pragma unroll
        for (int o = 16; o; o >>= 1)
            z += __shfl_xor_sync(0xffffffffu, z, o);
        if (tid == 0) { s_m = mm; s_z = z; }
    }
    __syncthreads();

    float inv = 1.0f / s_z;
    float gm = s_m;

    // D-slice reduce: tid -> (d_local, quarter); quarter sums 8 chunks
    int d_local = tid % DS4;
    int q = tid / DS4;             // 0..3
    int d = x * DS4 + d_local;

    float4 acc = make_float4(0.f, 0.f, 0.f, 0.f);
#pragma unroll
    for (int i = 0; i < NC3 / 4; i++) {
        int c = q * (NC3 / 4) + i;
        float w = s_w[c];
        float4 u = ((const float4*)g_u)[(size_t)(c * BB + b) * D4 + d];
        acc.x = fmaf(w, u.x, acc.x);
        acc.y = fmaf(w, u.y, acc.y);
        acc.z = fmaf(w, u.z, acc.z);
        acc.w = fmaf(w, u.w, acc.w);
    }
    s_acc[q][d_local] = acc;
    __syncthreads();

    if (q == 0) {
        float4 a0 = s_acc[0][d_local];
        float4 a1 = s_acc[1][d_local];
        float4 a2 = s_acc[2][d_local];
        float4 a3 = s_acc[3][d_local];
        float4 r;
        r.x = (a0.x + a1.x + a2.x + a3.x) * inv;
        r.y = (a0.y + a1.y + a2.y + a3.y) * inv;
        r.z = (a0.z + a1.z + a2.z + a3.z) * inv;
        r.w = (a0.w + a1.w + a2.w + a3.w) * inv;
        ((float4*)out_pooled)[b * D4 + d] = r;
    }

    // pp slice: 128 tokens per block-x
    if (tid < TT / NS4) {
        int t = x * (TT / NS4) + tid;
        out_pp[b * TT + t] = expf(g_scores[b * TT + t] - gm) * inv;
    }
}

// ---------------------------------------------------------------------------
extern "C" void kernel_launch(void* const* d_in, const int* in_sizes, int n_in,
                              void* d_out, int out_size) {
    const float* emb = (const float*)d_in[0];      // (B,T,D) f32
    const int* emask = (const int*)d_in[1];        // (B,T) i32
    const int* vmask = (const int*)d_in[2];        // (B,V) i32
    const float* W = (const float*)d_in[3];        // (V,D) f32

    float* out = (float*)d_out;
    float* out_ve = out;                            // (B,D)
    float* out_pooled = out + BB * DD;              // (B,D)
    float* out_vp = out + 2 * BB * DD;              // (B,V)
    float* out_pp = out + 2 * BB * DD + BB * VV;    // (B,T)

    k1_msum<<<dim3(NCH, BB), 192>>>((const float4*)emb, emask);
    k2_value<<<BB, 768>>>(W, vmask, out_ve, out_vp);
    k3_fused<<<dim3(NC3, BB), 192>>>((const float4*)emb, emask,
                                     (const float4*)out_ve);
    k4_combine<<<dim3(NS4, BB), 192>>>(out_pooled, out_pp);
}

// round 7
// speedup vs baseline: 1.0840x; 1.0077x over previous
#include <cuda_runtime.h>

#define BB 64
#define TT 512
#define DD 768
#define VV 20
#define NEGC (-1000000000.0f)
#define NCH 16            // t-chunks for k1
#define TCH (TT / NCH)    // 32 tokens per k1 chunk
#define NC3 32            // t-chunks for fused pooling kernel
#define TC3 (TT / NC3)    // 16 tokens per k3 chunk
#define D4 (DD / 4)       // 192 float4 per row
#define NS4 8             // k4 D-splits
#define DS4 (D4 / NS4)    // 24 float4 columns per k4 block
#define CQ (NC3 / NS4)    // 4 chunks per thread-quarter in k4

// Scratch (no device allocation allowed)
__device__ __align__(16) float g_p1[NCH * BB * DD];  // k1 partials
__device__ __align__(16) float g_u[NC3 * BB * DD];   // k3 unnormalized pooled partials
__device__ float g_m[NC3 * BB];                      // k3 chunk-local max
__device__ float g_z[NC3 * BB];                      // k3 chunk-local exp-sum
__device__ float g_scores[BB * TT];                  // raw pooling scores

// ---------------------------------------------------------------------------
// K1: partial masked sums. grid (NCH, B), block 192 (thread per float4 col)
// ---------------------------------------------------------------------------
__global__ __launch_bounds__(192) void k1_msum(const float4* __restrict__ emb,
                                               const int* __restrict__ emask) {
    int b = blockIdx.y;
    int c = blockIdx.x;
    int t0 = c * TCH;
    int tid = threadIdx.x;
    __shared__ float sm[TCH];
    if (tid < TCH)
        sm[tid] = (float)emask[b * TT + t0 + tid];
    __syncthreads();

    const float4* e = emb + (size_t)(b * TT + t0) * D4 + tid;
    float4 acc = make_float4(0.f, 0.f, 0.f, 0.f);
    float4 r[8];
#pragma unroll
    for (int i = 0; i < 8; i++) r[i] = e[(size_t)i * D4];

#pragma unroll
    for (int base = 0; base < TCH; base += 8) {
        float4 n[8];
        if (base + 8 < TCH) {
#pragma unroll
            for (int i = 0; i < 8; i++)
                n[i] = e[(size_t)(base + 8 + i) * D4];
        }
#pragma unroll
        for (int i = 0; i < 8; i++) {
            float m = sm[base + i];
            acc.x = fmaf(m, r[i].x, acc.x);
            acc.y = fmaf(m, r[i].y, acc.y);
            acc.z = fmaf(m, r[i].z, acc.z);
            acc.w = fmaf(m, r[i].w, acc.w);
        }
        if (base + 8 < TCH) {
#pragma unroll
            for (int i = 0; i < 8; i++) r[i] = n[i];
        }
    }
    ((float4*)g_p1)[(size_t)(c * BB + b) * D4 + tid] = acc;
}

// ---------------------------------------------------------------------------
// K2: reduce msum partials, value softmax over V=20, value_embedding.
// grid B, block 768
// ---------------------------------------------------------------------------
__global__ void k2_value(const float* __restrict__ W,
                         const int* __restrict__ vmask,
                         float* __restrict__ out_ve,
                         float* __restrict__ out_vp) {
    int b = blockIdx.x;
    int tid = threadIdx.x;
    int warp = tid >> 5;
    int lane = tid & 31;
    __shared__ float s_ms[DD];
    __shared__ float s_sc[VV];
    __shared__ float s_p[VV];

    {
        float acc = 0.f;
#pragma unroll
        for (int c = 0; c < NCH; c++)
            acc += g_p1[(size_t)(c * BB + b) * DD + tid];
        s_ms[tid] = acc;
    }
    __syncthreads();

    if (warp < VV) {
        const float* w = W + warp * DD;
        float acc = 0.f;
#pragma unroll
        for (int d = lane; d < DD; d += 32)
            acc += s_ms[d] * w[d];
#pragma unroll
        for (int o = 16; o; o >>= 1)
            acc += __shfl_xor_sync(0xffffffffu, acc, o);
        if (lane == 0)
            s_sc[warp] = acc + (1.0f - (float)vmask[b * VV + warp]) * NEGC;
    }
    __syncthreads();

    if (tid < 32) {
        float v = (tid < VV) ? s_sc[tid] : -3.4e38f;
        float mx = v;
#pragma unroll
        for (int o = 16; o; o >>= 1)
            mx = fmaxf(mx, __shfl_xor_sync(0xffffffffu, mx, o));
        float ev = (tid < VV) ? expf(v - mx) : 0.f;
        float s = ev;
#pragma unroll
        for (int o = 16; o; o >>= 1)
            s += __shfl_xor_sync(0xffffffffu, s, o);
        float p = ev / s;
        if (tid < VV) {
            s_p[tid] = p;
            out_vp[b * VV + tid] = p;
        }
    }
    __syncthreads();

    float acc = 0.f;
#pragma unroll
    for (int v = 0; v < VV; v++)
        acc += s_p[v] * W[v * DD + tid];
    out_ve[b * DD + tid] = acc;
}

// ---------------------------------------------------------------------------
// K3 (fused scores + online-softmax pooling, single emb pass).
// grid (NC3, B), block 192.
// ---------------------------------------------------------------------------
__global__ __launch_bounds__(192) void k3_fused(const float4* __restrict__ emb,
                                                const int* __restrict__ emask,
                                                const float4* __restrict__ ve) {
    int b = blockIdx.y;
    int c = blockIdx.x;
    int t0 = c * TC3;
    int tid = threadIdx.x;
    int warp = tid >> 5;
    int lane = tid & 31;

    __shared__ float red[TC3][6];
    __shared__ float s_e[TC3];

    float4 ve4 = ve[b * D4 + tid];

    const float4* e = emb + (size_t)(b * TT + t0) * D4 + tid;
    float4 r[TC3];
#pragma unroll
    for (int t = 0; t < TC3; t++)
        r[t] = e[(size_t)t * D4];

#pragma unroll
    for (int t = 0; t < TC3; t++) {
        float p = r[t].x * ve4.x + r[t].y * ve4.y +
                  r[t].z * ve4.z + r[t].w * ve4.w;
#pragma unroll
        for (int o = 16; o; o >>= 1)
            p += __shfl_xor_sync(0xffffffffu, p, o);
        if (lane == 0) red[t][warp] = p;
    }
    __syncthreads();

    if (tid < TC3) {
        float s = red[tid][0] + red[tid][1] + red[tid][2] +
                  red[tid][3] + red[tid][4] + red[tid][5];
        s += (1.0f - (float)emask[b * TT + t0 + tid]) * NEGC;
        g_scores[b * TT + t0 + tid] = s;

        float m = s;
#pragma unroll
        for (int o = 8; o; o >>= 1)
            m = fmaxf(m, __shfl_xor_sync(0x0000ffffu, m, o));
        float ez = expf(s - m);
        s_e[tid] = ez;
        float z = ez;
#pragma unroll
        for (int o = 8; o; o >>= 1)
            z += __shfl_xor_sync(0x0000ffffu, z, o);
        if (tid == 0) {
            g_m[c * BB + b] = m;
            g_z[c * BB + b] = z;
        }
    }
    __syncthreads();

    float4 acc = make_float4(0.f, 0.f, 0.f, 0.f);
#pragma unroll
    for (int t = 0; t < TC3; t++) {
        float w = s_e[t];
        acc.x = fmaf(w, r[t].x, acc.x);
        acc.y = fmaf(w, r[t].y, acc.y);
        acc.z = fmaf(w, r[t].z, acc.z);
        acc.w = fmaf(w, r[t].w, acc.w);
    }
    ((float4*)g_u)[(size_t)(c * BB + b) * D4 + tid] = acc;
}

// ---------------------------------------------------------------------------
// K4: combine chunk stats -> pooled embedding + pooling probs.
// grid (NS4, B) = 512 blocks, block 192.
// u loads prefetched at entry (independent of stats); warp 0 computes stats
// concurrently; single barrier; FMA + 8-way smem reduce.
// ---------------------------------------------------------------------------
__global__ __launch_bounds__(192) void k4_combine(float* __restrict__ out_pooled,
                                                  float* __restrict__ out_pp) {
    int b = blockIdx.y;
    int x = blockIdx.x;
    int tid = threadIdx.x;
    __shared__ float s_w[NC3];
    __shared__ float s_m, s_z;
    __shared__ float4 s_acc[NS4][DS4];

    // thread roles for the u reduce: tid -> (d_local, q)
    int d_local = tid % DS4;
    int q = tid / DS4;             // 0..7
    int d = x * DS4 + d_local;
    int c0 = q * CQ;

    // prefetch u (independent of stats) — 4 in-flight LDG.128 immediately
    float4 u[CQ];
#pragma unroll
    for (int i = 0; i < CQ; i++)
        u[i] = ((const float4*)g_u)[(size_t)((c0 + i) * BB + b) * D4 + d];

    // stats in warp 0, overlapped with the u loads above
    if (tid < 32) {
        float m = g_m[tid * BB + b];
        float mm = m;
#pragma unroll
        for (int o = 16; o; o >>= 1)
            mm = fmaxf(mm, __shfl_xor_sync(0xffffffffu, mm, o));
        float w = expf(m - mm);
        s_w[tid] = w;
        float z = g_z[tid * BB + b] * w;
#pragma unroll
        for (int o = 16; o; o >>= 1)
            z += __shfl_xor_sync(0xffffffffu, z, o);
        if (tid == 0) { s_m = mm; s_z = z; }
    }
    __syncthreads();

    float inv = 1.0f / s_z;
    float gm = s_m;

    float4 acc = make_float4(0.f, 0.f, 0.f, 0.f);
#pragma unroll
    for (int i = 0; i < CQ; i++) {
        float w = s_w[c0 + i];
        acc.x = fmaf(w, u[i].x, acc.x);
        acc.y = fmaf(w, u[i].y, acc.y);
        acc.z = fmaf(w, u[i].z, acc.z);
        acc.w = fmaf(w, u[i].w, acc.w);
    }
    s_acc[q][d_local] = acc;
    __syncthreads();

    if (q == 0) {
        float4 r = s_acc[0][d_local];
#pragma unroll
        for (int j = 1; j < NS4; j++) {
            float4 a = s_acc[j][d_local];
            r.x += a.x; r.y += a.y; r.z += a.z; r.w += a.w;
        }
        r.x *= inv; r.y *= inv; r.z *= inv; r.w *= inv;
        ((float4*)out_pooled)[b * D4 + d] = r;
    }

    // pp slice: 64 tokens per block-x
    if (tid < TT / NS4) {
        int t = x * (TT / NS4) + tid;
        out_pp[b * TT + t] = expf(g_scores[b * TT + t] - gm) * inv;
    }
}

// ---------------------------------------------------------------------------
extern "C" void kernel_launch(void* const* d_in, const int* in_sizes, int n_in,
                              void* d_out, int out_size) {
    const float* emb = (const float*)d_in[0];      // (B,T,D) f32
    const int* emask = (const int*)d_in[1];        // (B,T) i32
    const int* vmask = (const int*)d_in[2];        // (B,V) i32
    const float* W = (const float*)d_in[3];        // (V,D) f32

    float* out = (float*)d_out;
    float* out_ve = out;                            // (B,D)
    float* out_pooled = out + BB * DD;              // (B,D)
    float* out_vp = out + 2 * BB * DD;              // (B,V)
    float* out_pp = out + 2 * BB * DD + BB * VV;    // (B,T)

    k1_msum<<<dim3(NCH, BB), 192>>>((const float4*)emb, emask);
    k2_value<<<BB, 768>>>(W, vmask, out_ve, out_vp);
    k3_fused<<<dim3(NC3, BB), 192>>>((const float4*)emb, emask,
                                     (const float4*)out_ve);
    k4_combine<<<dim3(NS4, BB), 192>>>(out_pooled, out_pp);
}